// round 1
// baseline (speedup 1.0000x reference)
#include <cuda_runtime.h>
#include <stdint.h>

// Problem constants (fixed by setup_inputs)
#define B_  4
#define T_  24
#define C_  10
#define H_  128
#define W_  128
#define TC_ 365
#define DC_ 11
#define HID_ 64
#define DM_ 64
#define COUT_ (C_ + DM_)        // 74
#define PAD_VALUE (-1000.0f)

// scratch for the tiny MLP result: [B*T, 64]
__device__ float g_clim_feat[B_ * T_ * DM_];

// --- dtype-agnostic date read -------------------------------------------
// Dates are in [0, 365). If the buffer is int64, every odd 32-bit word of
// the first n/2 logical elements is zero. If it's real int32 sorted data,
// that's (astronomically) never true. We only touch n/2 logical elements,
// which is in-bounds under BOTH interpretations.
__device__ __forceinline__ bool detect_i64(const int* p, int n_elems) {
    int chk = n_elems / 2;
    if (chk > 48) chk = 48;
    for (int i = 0; i < chk; ++i)
        if (p[2 * i + 1] != 0) return false;
    return true;
}

__device__ __forceinline__ long long read_date(const void* p, int i, bool i64) {
    return i64 ? ((const long long*)p)[i] : (long long)((const int*)p)[i];
}

// --- Kernel A: date match + MLP -> clim_feat [B*T, 64] ------------------
__global__ void clim_feat_kernel(const float* __restrict__ input_clim,
                                 const void* __restrict__ dates_sat,
                                 const void* __restrict__ dates_clim,
                                 const float* __restrict__ W1,
                                 const float* __restrict__ b1,
                                 const float* __restrict__ W2,
                                 const float* __restrict__ b2) {
    const int bt  = blockIdx.x;        // 0..95
    const int b   = bt / T_;
    const int tid = threadIdx.x;       // 0..63

    __shared__ int   s_idx;
    __shared__ int   s_i64s, s_i64c;
    __shared__ float s_clim[DC_];
    __shared__ float s_h[HID_];

    if (tid == 0) {
        s_idx  = 0x7fffffff;
        s_i64s = detect_i64((const int*)dates_sat,  B_ * T_)  ? 1 : 0;
        s_i64c = detect_i64((const int*)dates_clim, B_ * TC_) ? 1 : 0;
    }
    __syncthreads();

    const bool i64s = (s_i64s != 0);
    const bool i64c = (s_i64c != 0);
    const long long target = read_date(dates_sat, bt, i64s);

    // parallel first-match scan over 365 climate dates
    for (int j = tid; j < TC_; j += HID_) {
        if (read_date(dates_clim, b * TC_ + j, i64c) == target)
            atomicMin(&s_idx, j);
    }
    __syncthreads();

    const bool has = (s_idx != 0x7fffffff);
    const int  idx = has ? s_idx : 0;

    if (tid < DC_) {
        s_clim[tid] = has ? input_clim[(b * TC_ + idx) * DC_ + tid] : PAD_VALUE;
    }
    __syncthreads();

    // h = relu(clim @ W1 + b1)   W1: [11,64] row-major
    float acc = b1[tid];
#pragma unroll
    for (int d = 0; d < DC_; ++d)
        acc = fmaf(s_clim[d], W1[d * HID_ + tid], acc);
    s_h[tid] = fmaxf(acc, 0.0f);
    __syncthreads();

    // out = h @ W2 + b2          W2: [64,64] row-major
    float o = b2[tid];
#pragma unroll
    for (int k = 0; k < HID_; ++k)
        o = fmaf(s_h[k], W2[k * DM_ + tid], o);
    g_clim_feat[bt * DM_ + tid] = o;
}

// --- Kernel B: assemble output [B,T,74,H,W] -----------------------------
// One float4 per thread. grid = (4096/256, 74, 96). c uniform per block.
__global__ void assemble_kernel(const float4* __restrict__ sat,
                                float4* __restrict__ out) {
    const int within = blockIdx.x * blockDim.x + threadIdx.x;  // 0..4095 (plane/4)
    const int c  = blockIdx.y;                                 // 0..73
    const int bt = blockIdx.z;                                 // 0..95

    const size_t oidx = ((size_t)bt * COUT_ + c) * (size_t)(H_ * W_ / 4) + within;

    if (c < C_) {
        const size_t sidx = ((size_t)bt * C_ + c) * (size_t)(H_ * W_ / 4) + within;
        out[oidx] = sat[sidx];
    } else {
        const float v = g_clim_feat[bt * DM_ + (c - C_)];
        out[oidx] = make_float4(v, v, v, v);
    }
}

extern "C" void kernel_launch(void* const* d_in, const int* in_sizes, int n_in,
                              void* d_out, int out_size) {
    const float* input_sat  = (const float*)d_in[0];
    const void*  dates_sat  = d_in[1];
    const float* input_clim = (const float*)d_in[2];
    const void*  dates_clim = d_in[3];
    const float* W1 = (const float*)d_in[4];
    const float* b1 = (const float*)d_in[5];
    const float* W2 = (const float*)d_in[6];
    const float* b2 = (const float*)d_in[7];

    clim_feat_kernel<<<B_ * T_, HID_>>>(input_clim, dates_sat, dates_clim,
                                        W1, b1, W2, b2);

    dim3 grid(H_ * W_ / 4 / 256, COUT_, B_ * T_);
    assemble_kernel<<<grid, 256>>>((const float4*)input_sat, (float4*)d_out);
}

// round 2
// speedup vs baseline: 1.1657x; 1.1657x over previous
#include <cuda_runtime.h>
#include <stdint.h>

// Problem constants (fixed by setup_inputs)
#define B_  4
#define T_  24
#define C_  10
#define H_  128
#define W_  128
#define TC_ 365
#define DC_ 11
#define HID_ 64
#define DM_ 64
#define COUT_ (C_ + DM_)        // 74
#define PAD_VALUE (-1000.0f)

#define PLANE4_ (H_ * W_ / 4)   // 4096 float4 per plane
#define THREADS_ 512
#define ITERS_ (PLANE4_ / THREADS_)  // 8

// scratch for the tiny MLP result: [B*T, 64]
__device__ float g_clim_feat[B_ * T_ * DM_];

// --- dtype-agnostic date read -------------------------------------------
// Dates are in [0, 365). If the buffer is int64, every odd 32-bit word of
// the first n/2 logical elements is zero. Reading only n/2 logical elements
// stays in-bounds under BOTH interpretations.
__device__ __forceinline__ bool detect_i64(const int* p, int n_elems) {
    int chk = n_elems / 2;
    if (chk > 48) chk = 48;
    for (int i = 0; i < chk; ++i)
        if (p[2 * i + 1] != 0) return false;
    return true;
}

__device__ __forceinline__ long long read_date(const void* p, int i, bool i64) {
    return i64 ? ((const long long*)p)[i] : (long long)((const int*)p)[i];
}

// --- Kernel A: date match + MLP -> clim_feat [B*T, 64] ------------------
__global__ void clim_feat_kernel(const float* __restrict__ input_clim,
                                 const void* __restrict__ dates_sat,
                                 const void* __restrict__ dates_clim,
                                 const float* __restrict__ W1,
                                 const float* __restrict__ b1,
                                 const float* __restrict__ W2,
                                 const float* __restrict__ b2) {
    const int bt  = blockIdx.x;        // 0..95
    const int b   = bt / T_;
    const int tid = threadIdx.x;       // 0..63

    __shared__ int   s_idx;
    __shared__ int   s_i64s, s_i64c;
    __shared__ float s_clim[DC_];
    __shared__ float s_h[HID_];

    if (tid == 0) {
        s_idx  = 0x7fffffff;
        s_i64s = detect_i64((const int*)dates_sat,  B_ * T_)  ? 1 : 0;
        s_i64c = detect_i64((const int*)dates_clim, B_ * TC_) ? 1 : 0;
    }
    __syncthreads();

    const bool i64s = (s_i64s != 0);
    const bool i64c = (s_i64c != 0);
    const long long target = read_date(dates_sat, bt, i64s);

    // parallel first-match scan over 365 climate dates
    for (int j = tid; j < TC_; j += HID_) {
        if (read_date(dates_clim, b * TC_ + j, i64c) == target)
            atomicMin(&s_idx, j);
    }
    __syncthreads();

    const bool has = (s_idx != 0x7fffffff);
    const int  idx = has ? s_idx : 0;

    if (tid < DC_) {
        s_clim[tid] = has ? input_clim[(b * TC_ + idx) * DC_ + tid] : PAD_VALUE;
    }
    __syncthreads();

    // h = relu(clim @ W1 + b1)   W1: [11,64] row-major
    float acc = b1[tid];
#pragma unroll
    for (int d = 0; d < DC_; ++d)
        acc = fmaf(s_clim[d], W1[d * HID_ + tid], acc);
    s_h[tid] = fmaxf(acc, 0.0f);
    __syncthreads();

    // out = h @ W2 + b2          W2: [64,64] row-major
    float o = b2[tid];
#pragma unroll
    for (int k = 0; k < HID_; ++k)
        o = fmaf(s_h[k], W2[k * DM_ + tid], o);
    g_clim_feat[bt * DM_ + tid] = o;
}

// --- Kernel B: assemble output [B,T,74,H,W] -----------------------------
// One block per (bt, c) plane. 512 threads x 8 float4 each = 4096 float4.
// Copy path: batch 8 independent streaming loads, then 8 streaming stores.
// Broadcast path: 8 streaming stores of one register.
__global__ __launch_bounds__(THREADS_)
void assemble_kernel(const float4* __restrict__ sat,
                     float4* __restrict__ out) {
    const int c   = blockIdx.x;   // 0..73
    const int bt  = blockIdx.y;   // 0..95
    const int tid = threadIdx.x;  // 0..511

    float4* __restrict__ dst =
        out + ((size_t)bt * COUT_ + c) * (size_t)PLANE4_ + tid;

    if (c < C_) {
        const float4* __restrict__ src =
            sat + ((size_t)bt * C_ + c) * (size_t)PLANE4_ + tid;
        float4 v[ITERS_];
#pragma unroll
        for (int i = 0; i < ITERS_; ++i)
            v[i] = __ldcs(src + i * THREADS_);
#pragma unroll
        for (int i = 0; i < ITERS_; ++i)
            __stcs(dst + i * THREADS_, v[i]);
    } else {
        const float s = g_clim_feat[bt * DM_ + (c - C_)];
        const float4 v = make_float4(s, s, s, s);
#pragma unroll
        for (int i = 0; i < ITERS_; ++i)
            __stcs(dst + i * THREADS_, v);
    }
}

extern "C" void kernel_launch(void* const* d_in, const int* in_sizes, int n_in,
                              void* d_out, int out_size) {
    const float* input_sat  = (const float*)d_in[0];
    const void*  dates_sat  = d_in[1];
    const float* input_clim = (const float*)d_in[2];
    const void*  dates_clim = d_in[3];
    const float* W1 = (const float*)d_in[4];
    const float* b1 = (const float*)d_in[5];
    const float* W2 = (const float*)d_in[6];
    const float* b2 = (const float*)d_in[7];

    clim_feat_kernel<<<B_ * T_, HID_>>>(input_clim, dates_sat, dates_clim,
                                        W1, b1, W2, b2);

    dim3 grid(COUT_, B_ * T_);
    assemble_kernel<<<grid, THREADS_>>>((const float4*)input_sat,
                                        (float4*)d_out);
}

// round 3
// speedup vs baseline: 1.2322x; 1.0571x over previous
#include <cuda_runtime.h>
#include <stdint.h>

// Problem constants (fixed by setup_inputs)
#define B_  4
#define T_  24
#define C_  10
#define H_  128
#define W_  128
#define TC_ 365
#define DC_ 11
#define HID_ 64
#define DM_ 64
#define COUT_ (C_ + DM_)        // 74
#define PAD_VALUE (-1000.0f)

#define PLANE4_ (H_ * W_ / 4)   // 4096 float4 per plane
#define THREADS_ 512
#define ITERS_ (PLANE4_ / THREADS_)  // 8

// --- dtype-agnostic date read -------------------------------------------
// Dates are in [0, 365). If the buffer is int64, every odd 32-bit word of
// the first n/2 logical elements is zero (real sorted int32 date data makes
// that astronomically unlikely). Reading only n/2 logical elements stays
// in-bounds under BOTH interpretations. Warp-parallel check + ballot.
__device__ __forceinline__ int detect_i64_warp(const int* p, int npairs) {
    const int lane = threadIdx.x & 31;
    int bad = 0;
    if (lane < npairs)       bad |= p[2 * lane + 1];
    if (lane + 32 < npairs)  bad |= p[2 * (lane + 32) + 1];
    unsigned m = __ballot_sync(0xFFFFFFFFu, bad != 0);
    return m == 0u;   // all odd words zero -> int64
}

__device__ __forceinline__ long long read_date(const void* p, int i, bool i64) {
    return i64 ? ((const long long*)p)[i] : (long long)((const int*)p)[i];
}

// --- Fused kernel: assemble output [B,T,74,H,W] -------------------------
// One block per (bt, c) plane. 512 threads x 8 float4 each = 4096 float4.
//  c < 10 : batched streaming plane copy from input_sat.
//  c >= 10: block computes its ONE clim_feat scalar inline (date match +
//           tiny MLP, all latency hidden by other blocks' stores), then
//           broadcasts it via 8 streaming STG.128 per thread.
__global__ __launch_bounds__(THREADS_)
void assemble_fused_kernel(const float4* __restrict__ sat,
                           const void*  __restrict__ dates_sat,
                           const void*  __restrict__ dates_clim,
                           const float* __restrict__ input_clim,
                           const float* __restrict__ W1,
                           const float* __restrict__ b1,
                           const float* __restrict__ W2,
                           const float* __restrict__ b2,
                           float4* __restrict__ out) {
    const int c   = blockIdx.x;   // 0..73  (uniform per block -> no divergence)
    const int bt  = blockIdx.y;   // 0..95
    const int tid = threadIdx.x;  // 0..511

    float4* __restrict__ dst =
        out + ((size_t)bt * COUT_ + c) * (size_t)PLANE4_ + tid;

    if (c < C_) {
        // ---- plane copy path ----
        const float4* __restrict__ src =
            sat + ((size_t)bt * C_ + c) * (size_t)PLANE4_ + tid;
        float4 v[ITERS_];
#pragma unroll
        for (int i = 0; i < ITERS_; ++i)
            v[i] = __ldcs(src + i * THREADS_);
#pragma unroll
        for (int i = 0; i < ITERS_; ++i)
            __stcs(dst + i * THREADS_, v[i]);
    } else {
        // ---- broadcast path: compute one clim_feat scalar, then store ----
        const int m = c - C_;          // output feature index 0..63
        const int b = bt / T_;

        __shared__ int   s_idx;
        __shared__ int   s_flags;
        __shared__ float s_clim[DC_];
        __shared__ float s_part[2];
        __shared__ float s_val;

        if (tid == 0) s_idx = 0x7fffffff;
        if (tid < 32) {
            int i64s = detect_i64_warp((const int*)dates_sat,  (B_ * T_) / 2);
            int i64c = detect_i64_warp((const int*)dates_clim, 64);  // min(B*Tc/2, 64)
            if (tid == 0) s_flags = i64s | (i64c << 1);
        }
        __syncthreads();

        const bool i64s = (s_flags & 1) != 0;
        const bool i64c = (s_flags & 2) != 0;
        const long long target = read_date(dates_sat, bt, i64s);

        // first-match scan over 365 climate dates (one element per thread)
        if (tid < TC_) {
            if (read_date(dates_clim, b * TC_ + tid, i64c) == target)
                atomicMin(&s_idx, tid);
        }
        __syncthreads();

        const bool has = (s_idx != 0x7fffffff);
        const int  idx = has ? s_idx : 0;
        if (tid < DC_)
            s_clim[tid] = has ? input_clim[(b * TC_ + idx) * DC_ + tid]
                              : PAD_VALUE;
        __syncthreads();

        // o[m] = b2[m] + sum_k relu(clim . W1[:,k] + b1[k]) * W2[k,m]
        float partial = 0.0f;
        if (tid < HID_) {
            float acc = b1[tid];
#pragma unroll
            for (int d = 0; d < DC_; ++d)
                acc = fmaf(s_clim[d], W1[d * HID_ + tid], acc);
            partial = fmaxf(acc, 0.0f) * W2[tid * DM_ + m];
        }
#pragma unroll
        for (int off = 16; off > 0; off >>= 1)
            partial += __shfl_down_sync(0xFFFFFFFFu, partial, off);
        if (tid < HID_ && (tid & 31) == 0)
            s_part[tid >> 5] = partial;
        __syncthreads();

        if (tid == 0)
            s_val = s_part[0] + s_part[1] + b2[m];
        __syncthreads();

        const float s = s_val;
        const float4 v = make_float4(s, s, s, s);
#pragma unroll
        for (int i = 0; i < ITERS_; ++i)
            __stcs(dst + i * THREADS_, v);
    }
}

extern "C" void kernel_launch(void* const* d_in, const int* in_sizes, int n_in,
                              void* d_out, int out_size) {
    const float* input_sat  = (const float*)d_in[0];
    const void*  dates_sat  = d_in[1];
    const float* input_clim = (const float*)d_in[2];
    const void*  dates_clim = d_in[3];
    const float* W1 = (const float*)d_in[4];
    const float* b1 = (const float*)d_in[5];
    const float* W2 = (const float*)d_in[6];
    const float* b2 = (const float*)d_in[7];

    dim3 grid(COUT_, B_ * T_);
    assemble_fused_kernel<<<grid, THREADS_>>>(
        (const float4*)input_sat, dates_sat, dates_clim, input_clim,
        W1, b1, W2, b2, (float4*)d_out);
}